// round 1
// baseline (speedup 1.0000x reference)
#include <cuda_runtime.h>

// Problem constants
#define B_     128
#define T_     26
#define IN_    512
#define H_     512
#define NC_    38
#define STEPS_ 26
#define BPE_   50257
#define WP_    30522
#define ROWS_  (B_ * STEPS_)   // 3328

// ---------------- device scratch (no allocations allowed) ----------------
__device__ float g_Hproj[ROWS_ * H_];     // i2h(batch_H), loop-invariant
__device__ float g_Hs[ROWS_ * H_];        // output hiddens [b, s, h]
__device__ float g_h[B_ * H_];
__device__ float g_c[B_ * H_];
__device__ float g_ph[B_ * H_];
__device__ float g_ctx[B_ * IN_];
__device__ float g_gates[B_ * 4 * H_];

// ---------------- init ----------------
__global__ void zero_hc_kernel() {
    int i = blockIdx.x * blockDim.x + threadIdx.x;
    if (i < B_ * H_) { g_h[i] = 0.f; g_c[i] = 0.f; }
}

// ---------------- generic big GEMM: C[M,N] = A[M,K] * W[N,K]^T + bias ----
// M % 128 == 0 (grid.y covers exactly), K % 16 == 0, N arbitrary (guarded).
__global__ __launch_bounds__(256)
void gemm_nt(const float* __restrict__ A, int lda,
             const float* __restrict__ W, int ldw,
             const float* __restrict__ bias,
             float* __restrict__ C, long long ldc,
             int N, int K)
{
    __shared__ float As[16][132];
    __shared__ float Ws[16][132];

    const int tid = threadIdx.x;
    const int m0 = blockIdx.y * 128;
    const int n0 = blockIdx.x * 128;
    const int tx = tid & 15;
    const int ty = tid >> 4;

    float acc[8][8];
#pragma unroll
    for (int i = 0; i < 8; i++)
#pragma unroll
        for (int j = 0; j < 8; j++) acc[i][j] = 0.f;

    const int lr = tid >> 2;        // 0..63
    const int lk = (tid & 3) * 4;   // 0,4,8,12

    for (int k0 = 0; k0 < K; k0 += 16) {
#pragma unroll
        for (int i = 0; i < 2; i++) {
            int r = lr + 64 * i;
            float4 v = *(const float4*)&A[(long long)(m0 + r) * lda + k0 + lk];
            As[lk + 0][r] = v.x; As[lk + 1][r] = v.y;
            As[lk + 2][r] = v.z; As[lk + 3][r] = v.w;
        }
#pragma unroll
        for (int i = 0; i < 2; i++) {
            int r = lr + 64 * i;
            float4 v = make_float4(0.f, 0.f, 0.f, 0.f);
            if (n0 + r < N)
                v = *(const float4*)&W[(long long)(n0 + r) * ldw + k0 + lk];
            Ws[lk + 0][r] = v.x; Ws[lk + 1][r] = v.y;
            Ws[lk + 2][r] = v.z; Ws[lk + 3][r] = v.w;
        }
        __syncthreads();
#pragma unroll
        for (int k = 0; k < 16; k++) {
            float a[8], b[8];
            *(float4*)&a[0] = *(const float4*)&As[k][ty * 8];
            *(float4*)&a[4] = *(const float4*)&As[k][ty * 8 + 4];
            *(float4*)&b[0] = *(const float4*)&Ws[k][tx * 8];
            *(float4*)&b[4] = *(const float4*)&Ws[k][tx * 8 + 4];
#pragma unroll
            for (int i = 0; i < 8; i++)
#pragma unroll
                for (int j = 0; j < 8; j++)
                    acc[i][j] += a[i] * b[j];
        }
        __syncthreads();
    }

#pragma unroll
    for (int i = 0; i < 8; i++) {
        int m = m0 + ty * 8 + i;
#pragma unroll
        for (int j = 0; j < 8; j++) {
            int n = n0 + tx * 8 + j;
            if (n < N) {
                float v = acc[i][j];
                if (bias) v += bias[n];
                C[(long long)m * ldc + n] = v;
            }
        }
    }
}

// ------- small recurrent GEMM: C[128,N] (+= if beta) A[128,K] * W[N,K]^T + bias
// grid.x = N/16 (N multiple of 16), K multiple of 32, lda = 512.
// W loads are scalar (ldw=550 for Wih is not 16B-aligned).
__global__ __launch_bounds__(256)
void rec_gemm(const float* __restrict__ A, int lda,
              const float* __restrict__ W, int ldw,
              const float* __restrict__ bias,
              float* __restrict__ C, int ldc,
              int K, int beta)
{
    __shared__ float As[32][132];
    __shared__ float Ws[32][20];

    const int tid = threadIdx.x;
    const int n0 = blockIdx.x * 16;
    const int tx = tid & 7;    // n pair
    const int ty = tid >> 3;   // 0..31

    float acc[4][2] = {};

    for (int k0 = 0; k0 < K; k0 += 32) {
#pragma unroll
        for (int i = 0; i < 4; i++) {
            int idx = tid + 256 * i;
            int r = idx >> 3;
            int kq = (idx & 7) * 4;
            float4 v = *(const float4*)&A[r * lda + k0 + kq];
            As[kq + 0][r] = v.x; As[kq + 1][r] = v.y;
            As[kq + 2][r] = v.z; As[kq + 3][r] = v.w;
        }
        if (tid < 128) {
            int n = tid >> 3;          // 0..15
            int kq = (tid & 7) * 4;
            const float* wp = &W[(long long)(n0 + n) * ldw + k0 + kq];
            Ws[kq + 0][n] = wp[0]; Ws[kq + 1][n] = wp[1];
            Ws[kq + 2][n] = wp[2]; Ws[kq + 3][n] = wp[3];
        }
        __syncthreads();
#pragma unroll
        for (int k = 0; k < 32; k++) {
            float b0 = Ws[k][2 * tx];
            float b1 = Ws[k][2 * tx + 1];
#pragma unroll
            for (int i = 0; i < 4; i++) {
                float a = As[k][ty + 32 * i];
                acc[i][0] += a * b0;
                acc[i][1] += a * b1;
            }
        }
        __syncthreads();
    }

#pragma unroll
    for (int i = 0; i < 4; i++) {
        int m = ty + 32 * i;
#pragma unroll
        for (int j = 0; j < 2; j++) {
            int n = n0 + 2 * tx + j;
            float v = acc[i][j];
            if (bias) v += bias[n];
            float* p = &C[m * ldc + n];
            if (beta) v += *p;
            *p = v;
        }
    }
}

// ------- attention: e = tanh(Hproj + ph) . score_W ; softmax over T ; context
__global__ __launch_bounds__(256)
void attn_kernel(const float* __restrict__ batch_H,
                 const float* __restrict__ score_W)
{
    const int b = blockIdx.x;
    const int tid = threadIdx.x;
    __shared__ float s_ph[512];
    __shared__ float s_sc[512];
    __shared__ float s_e[32];

#pragma unroll
    for (int i = 0; i < 2; i++) {
        int j = tid + 256 * i;
        s_ph[j] = g_ph[b * 512 + j];
        s_sc[j] = score_W[j];
    }
    __syncthreads();

    const int w = tid >> 5, lane = tid & 31;
    for (int t = w; t < T_; t += 8) {
        const float* hp = &g_Hproj[(b * T_ + t) * 512];
        float sum = 0.f;
        for (int j = lane; j < 512; j += 32)
            sum += s_sc[j] * tanhf(hp[j] + s_ph[j]);
#pragma unroll
        for (int o = 16; o > 0; o >>= 1)
            sum += __shfl_xor_sync(0xffffffffu, sum, o);
        if (lane == 0) s_e[t] = sum;
    }
    __syncthreads();

    if (tid < 32) {
        float v = (tid < T_) ? s_e[tid] : -1e30f;
        float m = v;
#pragma unroll
        for (int o = 16; o > 0; o >>= 1)
            m = fmaxf(m, __shfl_xor_sync(0xffffffffu, m, o));
        float e = (tid < T_) ? expf(v - m) : 0.f;
        float s = e;
#pragma unroll
        for (int o = 16; o > 0; o >>= 1)
            s += __shfl_xor_sync(0xffffffffu, s, o);
        if (tid < T_) s_e[tid] = e / s;
    }
    __syncthreads();

#pragma unroll
    for (int i = 0; i < 2; i++) {
        int j = tid + 256 * i;
        float acc = 0.f;
#pragma unroll
        for (int t = 0; t < T_; t++)
            acc += s_e[t] * batch_H[(b * T_ + t) * 512 + j];
        g_ctx[b * 512 + j] = acc;
    }
}

// ------- LSTM pointwise update; one-hot folded in as Wih column 512+cls ----
__global__ __launch_bounds__(256)
void lstm_kernel(const float* __restrict__ Wih,
                 const int* __restrict__ text, int s)
{
    const int b = blockIdx.x;
    const int tid = threadIdx.x;
    const int cls = text[b * STEPS_ + s];
    const float* wcol = Wih + 512 + cls;   // column of [2048, 550] matrix

#pragma unroll
    for (int i = 0; i < 2; i++) {
        int j = tid + 256 * i;
        float gi = g_gates[b * 2048 + j]        + wcol[(j) * 550];
        float gf = g_gates[b * 2048 + 512 + j]  + wcol[(512 + j) * 550];
        float gg = g_gates[b * 2048 + 1024 + j] + wcol[(1024 + j) * 550];
        float go = g_gates[b * 2048 + 1536 + j] + wcol[(1536 + j) * 550];
        float si = 1.f / (1.f + expf(-gi));
        float sf = 1.f / (1.f + expf(-gf));
        float so = 1.f / (1.f + expf(-go));
        float tg = tanhf(gg);
        float cn = sf * g_c[b * 512 + j] + si * tg;
        float hn = so * tanhf(cn);
        g_c[b * 512 + j] = cn;
        g_h[b * 512 + j] = hn;
        g_Hs[(b * STEPS_ + s) * 512 + j] = hn;
    }
}

// ---------------- launcher ----------------
extern "C" void kernel_launch(void* const* d_in, const int* in_sizes, int n_in,
                              void* d_out, int out_size)
{
    const float* batch_H = (const float*)d_in[0];
    const int*   text    = (const int*)  d_in[1];
    const float* i2h_W   = (const float*)d_in[2];
    const float* h2h_W   = (const float*)d_in[3];
    const float* h2h_b   = (const float*)d_in[4];
    const float* score_W = (const float*)d_in[5];
    const float* rnn_Wih = (const float*)d_in[6];
    const float* rnn_bih = (const float*)d_in[7];
    const float* rnn_Whh = (const float*)d_in[8];
    const float* rnn_bhh = (const float*)d_in[9];
    const float* char_W  = (const float*)d_in[10];
    const float* char_b  = (const float*)d_in[11];
    const float* bpe_W   = (const float*)d_in[12];
    const float* bpe_b   = (const float*)d_in[13];
    const float* wp_W    = (const float*)d_in[14];
    const float* wp_b    = (const float*)d_in[15];
    float* out = (float*)d_out;

    float *d_Hproj, *d_Hs, *d_h, *d_ph, *d_ctx, *d_gates;
    cudaGetSymbolAddress((void**)&d_Hproj, g_Hproj);
    cudaGetSymbolAddress((void**)&d_Hs,    g_Hs);
    cudaGetSymbolAddress((void**)&d_h,     g_h);
    cudaGetSymbolAddress((void**)&d_ph,    g_ph);
    cudaGetSymbolAddress((void**)&d_ctx,   g_ctx);
    cudaGetSymbolAddress((void**)&d_gates, g_gates);

    // h0 = c0 = 0
    zero_hc_kernel<<<(B_ * H_ + 255) / 256, 256>>>();

    // Hproj = batch_H @ i2h_W^T   ([3328,512] x [512,512]^T)
    gemm_nt<<<dim3(4, 26), 256>>>(batch_H, 512, i2h_W, 512, nullptr,
                                  d_Hproj, 512, 512, 512);

    // 26-step attention-LSTM scan
    for (int s = 0; s < STEPS_; s++) {
        // ph = h @ h2h_W^T + h2h_b
        rec_gemm<<<32, 256>>>(d_h, 512, h2h_W, 512, h2h_b, d_ph, 512, 512, 0);
        // alpha + context
        attn_kernel<<<B_, 256>>>(batch_H, score_W);
        // gates = ctx @ Wih[:, :512]^T + bih   (+=)  h @ Whh^T + bhh
        rec_gemm<<<128, 256>>>(d_ctx, 512, rnn_Wih, 550, rnn_bih, d_gates, 2048, 512, 0);
        rec_gemm<<<128, 256>>>(d_h,   512, rnn_Whh, 512, rnn_bhh, d_gates, 2048, 512, 1);
        // LSTM update (adds Wih one-hot column), writes h into g_Hs
        lstm_kernel<<<B_, 256>>>(rnn_Wih, text, s);
    }

    // Output heads, concatenated [char | bpe | wp] in d_out
    const long long off_bpe = (long long)ROWS_ * NC_;
    const long long off_wp  = off_bpe + (long long)ROWS_ * BPE_;

    gemm_nt<<<dim3(1, 26), 256>>>(d_Hs, 512, char_W, 512, char_b,
                                  out, NC_, NC_, 512);
    gemm_nt<<<dim3((BPE_ + 127) / 128, 26), 256>>>(d_Hs, 512, bpe_W, 512, bpe_b,
                                  out + off_bpe, BPE_, BPE_, 512);
    gemm_nt<<<dim3((WP_ + 127) / 128, 26), 256>>>(d_Hs, 512, wp_W, 512, wp_b,
                                  out + off_wp, WP_, WP_, 512);
}

// round 3
// speedup vs baseline: 2.1763x; 2.1763x over previous
#include <cuda_runtime.h>
#include <cuda_fp16.h>
#include <cstdint>

// Problem constants
#define B_     128
#define T_     26
#define IN_    512
#define H_     512
#define NC_    38
#define STEPS_ 26
#define BPE_   50257
#define WP_    30522
#define ROWS_  (B_ * STEPS_)   // 3328

// ---------------- device scratch (no allocations allowed) ----------------
__device__ float g_Hproj[ROWS_ * H_];     // i2h(batch_H), loop-invariant
__device__ float g_Hs[ROWS_ * H_];        // output hiddens [b, s, h]
__device__ float g_h[B_ * H_];
__device__ float g_c[B_ * H_];
__device__ float g_ph[B_ * H_];
__device__ float g_ctx[B_ * IN_];
__device__ float g_gates[B_ * 4 * H_];

// fp16 copies for tensor-core head GEMMs
__device__ __align__(16) __half g_Hs_h[ROWS_ * H_];
__device__ __align__(16) __half g_char_h[NC_ * H_];
__device__ __align__(16) __half g_bpe_h[(size_t)BPE_ * H_];
__device__ __align__(16) __half g_wp_h[(size_t)WP_ * H_];

// ======================= helpers =================
__device__ __forceinline__ uint32_t smem_u32(const void* p) {
    return (uint32_t)__cvta_generic_to_shared(p);
}

__device__ __forceinline__ void cp_async16(uint32_t dst, const void* src, int src_bytes) {
    asm volatile("cp.async.cg.shared.global [%0], [%1], 16, %2;"
                 :: "r"(dst), "l"(src), "r"(src_bytes));
}
#define CP_COMMIT() asm volatile("cp.async.commit_group;" ::: "memory")
#define CP_WAIT1()  asm volatile("cp.async.wait_group 1;" ::: "memory")

__device__ __forceinline__ void ldsm_x4(uint32_t* r, uint32_t addr) {
    asm volatile("ldmatrix.sync.aligned.m8n8.x4.shared.b16 {%0,%1,%2,%3}, [%4];"
                 : "=r"(r[0]), "=r"(r[1]), "=r"(r[2]), "=r"(r[3]) : "r"(addr));
}

__device__ __forceinline__ void mma16816(float* d, const uint32_t* a, const uint32_t* b) {
    asm volatile(
        "mma.sync.aligned.m16n8k16.row.col.f32.f16.f16.f32 "
        "{%0,%1,%2,%3}, {%4,%5,%6,%7}, {%8,%9}, {%0,%1,%2,%3};"
        : "+f"(d[0]), "+f"(d[1]), "+f"(d[2]), "+f"(d[3])
        : "r"(a[0]), "r"(a[1]), "r"(a[2]), "r"(a[3]), "r"(b[0]), "r"(b[1]));
}

// ============ tensor-core head GEMM: out[3328,N] = A_h @ W_h^T + bias ======
// BM=128 x BN=128 x BK=32; 8 warps (2x4), warp tile 64x32; double-buffered
// cp.async; ldmatrix.x4; mma.sync m16n8k16 fp16->fp32.
#define HBK 32
#define HNIT (512 / HBK)   // 16

__global__ __launch_bounds__(256, 2)
void head_gemm_mma(const __half* __restrict__ A,   // [3328, 512]
                   const __half* __restrict__ W,   // [Ntot, 512]
                   const float* __restrict__ bias, // [Ntot]
                   float* __restrict__ out,        // [3328, Ntot]
                   int Ntot)
{
    __shared__ __align__(16) __half As[2][128][40];
    __shared__ __align__(16) __half Bs[2][128][40];

    const int tid = threadIdx.x;
    const int wid = tid >> 5, lane = tid & 31;
    const int wm = wid >> 2, wn = wid & 3;       // 2 x 4 warp grid
    const int m0 = blockIdx.x * 128;
    const int n0 = blockIdx.y * 128;

    float acc[4][4][4];
#pragma unroll
    for (int i = 0; i < 4; i++)
#pragma unroll
        for (int j = 0; j < 4; j++)
#pragma unroll
            for (int q = 0; q < 4; q++) acc[i][j][q] = 0.f;

    // per-thread load coords: 512 16B-chunks per tile, 2 per thread
    const int r0c = tid >> 2;              // row for chunk 0 (0..63)
    const int q0c = (tid & 3) * 8;         // col halves

    // ---- preload tile 0 ----
    {
        const int koff = 0;
#pragma unroll
        for (int c = 0; c < 2; c++) {
            int row = r0c + 64 * c;
            cp_async16(smem_u32(&As[0][row][q0c]),
                       A + (size_t)(m0 + row) * 512 + koff + q0c, 16);
            cp_async16(smem_u32(&Bs[0][row][q0c]),
                       W + (size_t)(n0 + row) * 512 + koff + q0c,
                       (n0 + row < Ntot) ? 16 : 0);
        }
        CP_COMMIT();
    }

    for (int it = 0; it < HNIT; it++) {
        if (it + 1 < HNIT) {
            const int koff = (it + 1) * HBK;
            const int st = (it + 1) & 1;
#pragma unroll
            for (int c = 0; c < 2; c++) {
                int row = r0c + 64 * c;
                cp_async16(smem_u32(&As[st][row][q0c]),
                           A + (size_t)(m0 + row) * 512 + koff + q0c, 16);
                cp_async16(smem_u32(&Bs[st][row][q0c]),
                           W + (size_t)(n0 + row) * 512 + koff + q0c,
                           (n0 + row < Ntot) ? 16 : 0);
            }
        }
        CP_COMMIT();
        CP_WAIT1();
        __syncthreads();

        const int st = it & 1;
#pragma unroll
        for (int ks = 0; ks < 2; ks++) {
            uint32_t a[4][4], b[2][4];
#pragma unroll
            for (int i = 0; i < 4; i++) {
                int r = wm * 64 + i * 16 + (lane & 15);
                int cq = ks * 16 + (lane >> 4) * 8;
                ldsm_x4(a[i], smem_u32(&As[st][r][cq]));
            }
#pragma unroll
            for (int j = 0; j < 2; j++) {
                int r = wn * 32 + j * 16 + (lane & 7) + ((lane >> 4) << 3);
                int cq = ks * 16 + ((lane >> 3) & 1) * 8;
                ldsm_x4(b[j], smem_u32(&Bs[st][r][cq]));
            }
#pragma unroll
            for (int i = 0; i < 4; i++)
#pragma unroll
                for (int j = 0; j < 4; j++)
                    mma16816(acc[i][j], a[i], &b[j >> 1][(j & 1) * 2]);
        }
        __syncthreads();
    }

    // ---- epilogue: add bias, store fp32 ----
#pragma unroll
    for (int i = 0; i < 4; i++) {
        int mBase = m0 + wm * 64 + i * 16 + (lane >> 2);
#pragma unroll
        for (int j = 0; j < 4; j++) {
            int n = n0 + wn * 32 + j * 8 + (lane & 3) * 2;
            if (n < Ntot) {
                float b0 = bias[n];
                float b1 = (n + 1 < Ntot) ? bias[n + 1] : 0.f;
                float* p0 = out + (size_t)mBase * Ntot + n;
                float* p1 = out + (size_t)(mBase + 8) * Ntot + n;
                p0[0] = acc[i][j][0] + b0;
                p1[0] = acc[i][j][2] + b0;
                if (n + 1 < Ntot) {
                    p0[1] = acc[i][j][1] + b1;
                    p1[1] = acc[i][j][3] + b1;
                }
            }
        }
    }
}

// ---------------- fp32 -> fp16 conversion ----------------
__global__ void cvt_half(const float* __restrict__ src, __half* __restrict__ dst, int n4) {
    int i = blockIdx.x * blockDim.x + threadIdx.x;
    if (i < n4) {
        float4 v = ((const float4*)src)[i];
        __half2 a = __floats2half2_rn(v.x, v.y);
        __half2 b = __floats2half2_rn(v.z, v.w);
        ((__half2*)dst)[2 * i] = a;
        ((__half2*)dst)[2 * i + 1] = b;
    }
}

// ---------------- init ----------------
__global__ void zero_hc_kernel() {
    int i = blockIdx.x * blockDim.x + threadIdx.x;
    if (i < B_ * H_) { g_h[i] = 0.f; g_c[i] = 0.f; }
}

// ---------------- fp32 GEMM (Hproj only): C = A[M,K] @ W[N,K]^T ----------
__global__ __launch_bounds__(256)
void gemm_nt(const float* __restrict__ A, int lda,
             const float* __restrict__ W, int ldw,
             const float* __restrict__ bias,
             float* __restrict__ C, long long ldc,
             int N, int K)
{
    __shared__ float As[16][132];
    __shared__ float Ws[16][132];

    const int tid = threadIdx.x;
    const int m0 = blockIdx.y * 128;
    const int n0 = blockIdx.x * 128;
    const int tx = tid & 15;
    const int ty = tid >> 4;

    float acc[8][8];
#pragma unroll
    for (int i = 0; i < 8; i++)
#pragma unroll
        for (int j = 0; j < 8; j++) acc[i][j] = 0.f;

    const int lr = tid >> 2;
    const int lk = (tid & 3) * 4;

    for (int k0 = 0; k0 < K; k0 += 16) {
#pragma unroll
        for (int i = 0; i < 2; i++) {
            int r = lr + 64 * i;
            float4 v = *(const float4*)&A[(long long)(m0 + r) * lda + k0 + lk];
            As[lk + 0][r] = v.x; As[lk + 1][r] = v.y;
            As[lk + 2][r] = v.z; As[lk + 3][r] = v.w;
        }
#pragma unroll
        for (int i = 0; i < 2; i++) {
            int r = lr + 64 * i;
            float4 v = make_float4(0.f, 0.f, 0.f, 0.f);
            if (n0 + r < N)
                v = *(const float4*)&W[(long long)(n0 + r) * ldw + k0 + lk];
            Ws[lk + 0][r] = v.x; Ws[lk + 1][r] = v.y;
            Ws[lk + 2][r] = v.z; Ws[lk + 3][r] = v.w;
        }
        __syncthreads();
#pragma unroll
        for (int k = 0; k < 16; k++) {
            float a[8], b[8];
            *(float4*)&a[0] = *(const float4*)&As[k][ty * 8];
            *(float4*)&a[4] = *(const float4*)&As[k][ty * 8 + 4];
            *(float4*)&b[0] = *(const float4*)&Ws[k][tx * 8];
            *(float4*)&b[4] = *(const float4*)&Ws[k][tx * 8 + 4];
#pragma unroll
            for (int i = 0; i < 8; i++)
#pragma unroll
                for (int j = 0; j < 8; j++)
                    acc[i][j] += a[i] * b[j];
        }
        __syncthreads();
    }

#pragma unroll
    for (int i = 0; i < 8; i++) {
        int m = m0 + ty * 8 + i;
#pragma unroll
        for (int j = 0; j < 8; j++) {
            int n = n0 + tx * 8 + j;
            if (n < N) {
                float v = acc[i][j];
                if (bias) v += bias[n];
                C[(long long)m * ldc + n] = v;
            }
        }
    }
}

// ------- small recurrent GEMM: C[128,N] (+= if beta) A[128,K] * W[N,K]^T + bias
__global__ __launch_bounds__(256)
void rec_gemm(const float* __restrict__ A, int lda,
              const float* __restrict__ W, int ldw,
              const float* __restrict__ bias,
              float* __restrict__ C, int ldc,
              int K, int beta)
{
    __shared__ float As[32][132];
    __shared__ float Ws[32][20];

    const int tid = threadIdx.x;
    const int n0 = blockIdx.x * 16;
    const int tx = tid & 7;
    const int ty = tid >> 3;

    float acc[4][2] = {};

    for (int k0 = 0; k0 < K; k0 += 32) {
#pragma unroll
        for (int i = 0; i < 4; i++) {
            int idx = tid + 256 * i;
            int r = idx >> 3;
            int kq = (idx & 7) * 4;
            float4 v = *(const float4*)&A[r * lda + k0 + kq];
            As[kq + 0][r] = v.x; As[kq + 1][r] = v.y;
            As[kq + 2][r] = v.z; As[kq + 3][r] = v.w;
        }
        if (tid < 128) {
            int n = tid >> 3;
            int kq = (tid & 7) * 4;
            const float* wp = &W[(long long)(n0 + n) * ldw + k0 + kq];
            Ws[kq + 0][n] = wp[0]; Ws[kq + 1][n] = wp[1];
            Ws[kq + 2][n] = wp[2]; Ws[kq + 3][n] = wp[3];
        }
        __syncthreads();
#pragma unroll
        for (int k = 0; k < 32; k++) {
            float b0 = Ws[k][2 * tx];
            float b1 = Ws[k][2 * tx + 1];
#pragma unroll
            for (int i = 0; i < 4; i++) {
                float a = As[k][ty + 32 * i];
                acc[i][0] += a * b0;
                acc[i][1] += a * b1;
            }
        }
        __syncthreads();
    }

#pragma unroll
    for (int i = 0; i < 4; i++) {
        int m = ty + 32 * i;
#pragma unroll
        for (int j = 0; j < 2; j++) {
            int n = n0 + 2 * tx + j;
            float v = acc[i][j];
            if (bias) v += bias[n];
            float* p = &C[m * ldc + n];
            if (beta) v += *p;
            *p = v;
        }
    }
}

// ------- attention: e = tanh(Hproj + ph) . score_W ; softmax ; context -----
__global__ __launch_bounds__(256)
void attn_kernel(const float* __restrict__ batch_H,
                 const float* __restrict__ score_W)
{
    const int b = blockIdx.x;
    const int tid = threadIdx.x;
    __shared__ float s_ph[512];
    __shared__ float s_sc[512];
    __shared__ float s_e[32];

#pragma unroll
    for (int i = 0; i < 2; i++) {
        int j = tid + 256 * i;
        s_ph[j] = g_ph[b * 512 + j];
        s_sc[j] = score_W[j];
    }
    __syncthreads();

    const int w = tid >> 5, lane = tid & 31;
    for (int t = w; t < T_; t += 8) {
        const float* hp = &g_Hproj[(b * T_ + t) * 512];
        float sum = 0.f;
        for (int j = lane; j < 512; j += 32)
            sum += s_sc[j] * tanhf(hp[j] + s_ph[j]);
#pragma unroll
        for (int o = 16; o > 0; o >>= 1)
            sum += __shfl_xor_sync(0xffffffffu, sum, o);
        if (lane == 0) s_e[t] = sum;
    }
    __syncthreads();

    if (tid < 32) {
        float v = (tid < T_) ? s_e[tid] : -1e30f;
        float m = v;
#pragma unroll
        for (int o = 16; o > 0; o >>= 1)
            m = fmaxf(m, __shfl_xor_sync(0xffffffffu, m, o));
        float e = (tid < T_) ? expf(v - m) : 0.f;
        float s = e;
#pragma unroll
        for (int o = 16; o > 0; o >>= 1)
            s += __shfl_xor_sync(0xffffffffu, s, o);
        if (tid < T_) s_e[tid] = e / s;
    }
    __syncthreads();

#pragma unroll
    for (int i = 0; i < 2; i++) {
        int j = tid + 256 * i;
        float acc = 0.f;
#pragma unroll
        for (int t = 0; t < T_; t++)
            acc += s_e[t] * batch_H[(b * T_ + t) * 512 + j];
        g_ctx[b * 512 + j] = acc;
    }
}

// ------- LSTM pointwise update; one-hot folded in as Wih column 512+cls ----
__global__ __launch_bounds__(256)
void lstm_kernel(const float* __restrict__ Wih,
                 const int* __restrict__ text, int s)
{
    const int b = blockIdx.x;
    const int tid = threadIdx.x;
    const int cls = text[b * STEPS_ + s];
    const float* wcol = Wih + 512 + cls;

#pragma unroll
    for (int i = 0; i < 2; i++) {
        int j = tid + 256 * i;
        float gi = g_gates[b * 2048 + j]        + wcol[(j) * 550];
        float gf = g_gates[b * 2048 + 512 + j]  + wcol[(512 + j) * 550];
        float gg = g_gates[b * 2048 + 1024 + j] + wcol[(1024 + j) * 550];
        float go = g_gates[b * 2048 + 1536 + j] + wcol[(1536 + j) * 550];
        float si = 1.f / (1.f + expf(-gi));
        float sf = 1.f / (1.f + expf(-gf));
        float so = 1.f / (1.f + expf(-go));
        float tg = tanhf(gg);
        float cn = sf * g_c[b * 512 + j] + si * tg;
        float hn = so * tanhf(cn);
        g_c[b * 512 + j] = cn;
        g_h[b * 512 + j] = hn;
        g_Hs[(b * STEPS_ + s) * 512 + j] = hn;
    }
}

// ---------------- launcher ----------------
extern "C" void kernel_launch(void* const* d_in, const int* in_sizes, int n_in,
                              void* d_out, int out_size)
{
    const float* batch_H = (const float*)d_in[0];
    const int*   text    = (const int*)  d_in[1];
    const float* i2h_W   = (const float*)d_in[2];
    const float* h2h_W   = (const float*)d_in[3];
    const float* h2h_b   = (const float*)d_in[4];
    const float* score_W = (const float*)d_in[5];
    const float* rnn_Wih = (const float*)d_in[6];
    const float* rnn_bih = (const float*)d_in[7];
    const float* rnn_Whh = (const float*)d_in[8];
    const float* rnn_bhh = (const float*)d_in[9];
    const float* char_W  = (const float*)d_in[10];
    const float* char_b  = (const float*)d_in[11];
    const float* bpe_W   = (const float*)d_in[12];
    const float* bpe_b   = (const float*)d_in[13];
    const float* wp_W    = (const float*)d_in[14];
    const float* wp_b    = (const float*)d_in[15];
    float* out = (float*)d_out;

    float *d_Hproj, *d_Hs, *d_h, *d_ph, *d_ctx, *d_gates;
    __half *d_Hs_h, *d_char_h, *d_bpe_h, *d_wp_h;
    cudaGetSymbolAddress((void**)&d_Hproj, g_Hproj);
    cudaGetSymbolAddress((void**)&d_Hs,    g_Hs);
    cudaGetSymbolAddress((void**)&d_h,     g_h);
    cudaGetSymbolAddress((void**)&d_ph,    g_ph);
    cudaGetSymbolAddress((void**)&d_ctx,   g_ctx);
    cudaGetSymbolAddress((void**)&d_gates, g_gates);
    cudaGetSymbolAddress((void**)&d_Hs_h,  g_Hs_h);
    cudaGetSymbolAddress((void**)&d_char_h, g_char_h);
    cudaGetSymbolAddress((void**)&d_bpe_h, g_bpe_h);
    cudaGetSymbolAddress((void**)&d_wp_h,  g_wp_h);

    zero_hc_kernel<<<(B_ * H_ + 255) / 256, 256>>>();

    // weight conversions (independent of scan)
    {
        int n4 = NC_ * H_ / 4;
        cvt_half<<<(n4 + 255) / 256, 256>>>(char_W, d_char_h, n4);
        n4 = BPE_ * H_ / 4;
        cvt_half<<<(n4 + 255) / 256, 256>>>(bpe_W, d_bpe_h, n4);
        n4 = WP_ * H_ / 4;
        cvt_half<<<(n4 + 255) / 256, 256>>>(wp_W, d_wp_h, n4);
    }

    // Hproj = batch_H @ i2h_W^T
    gemm_nt<<<dim3(4, 26), 256>>>(batch_H, 512, i2h_W, 512, nullptr,
                                  d_Hproj, 512, 512, 512);

    // 26-step attention-LSTM scan
    for (int s = 0; s < STEPS_; s++) {
        rec_gemm<<<32, 256>>>(d_h, 512, h2h_W, 512, h2h_b, d_ph, 512, 512, 0);
        attn_kernel<<<B_, 256>>>(batch_H, score_W);
        rec_gemm<<<128, 256>>>(d_ctx, 512, rnn_Wih, 550, rnn_bih, d_gates, 2048, 512, 0);
        rec_gemm<<<128, 256>>>(d_h,   512, rnn_Whh, 512, rnn_bhh, d_gates, 2048, 512, 1);
        lstm_kernel<<<B_, 256>>>(rnn_Wih, text, s);
    }

    // hidden states -> fp16
    {
        int n4 = ROWS_ * H_ / 4;
        cvt_half<<<(n4 + 255) / 256, 256>>>(d_Hs, d_Hs_h, n4);
    }

    // output heads via mma.sync fp16 GEMM: [char | bpe | wp]
    const long long off_bpe = (long long)ROWS_ * NC_;
    const long long off_wp  = off_bpe + (long long)ROWS_ * BPE_;

    head_gemm_mma<<<dim3(26, 1), 256>>>(d_Hs_h, d_char_h, char_b, out, NC_);
    head_gemm_mma<<<dim3(26, (BPE_ + 127) / 128), 256>>>(
        d_Hs_h, d_bpe_h, bpe_b, out + off_bpe, BPE_);
    head_gemm_mma<<<dim3(26, (WP_ + 127) / 128), 256>>>(
        d_Hs_h, d_wp_h, wp_b, out + off_wp, WP_);
}

// round 4
// speedup vs baseline: 4.8163x; 2.2131x over previous
#include <cuda_runtime.h>
#include <cuda_fp16.h>
#include <cstdint>

// Problem constants
#define B_     128
#define T_     26
#define IN_    512
#define H_     512
#define NC_    38
#define STEPS_ 26
#define BPE_   50257
#define WP_    30522
#define ROWS_  (B_ * STEPS_)   // 3328
#define GRID_SCAN 128

// ---------------- device scratch ----------------
__device__ float g_Hproj[ROWS_ * H_];                 // i2h(batch_H) fp32
__device__ float g_ph[B_ * H_];                       // h @ h2h^T + b
__device__ float g_gates[B_ * 4 * H_];                // mma gates (no bias)
__device__ __align__(16) __half g_xh[B_ * 1024];      // [ctx | h] fp16 per batch
__device__ __align__(16) __half g_h2h_h[H_ * H_];     // h2h fp16
__device__ __align__(16) __half g_Wg[4 * H_ * 1024];  // [Wih(:512) | Whh] fp16
__device__ float g_Wt[NC_ * 4 * H_];                  // onehot col + bih + bhh
__device__ __align__(16) __half g_Hs_h[ROWS_ * H_];   // hidden states fp16
__device__ __align__(16) __half g_char_h[NC_ * H_];
__device__ __align__(16) __half g_bpe_h[(size_t)BPE_ * H_];
__device__ __align__(16) __half g_wp_h[(size_t)WP_ * H_];

// grid barrier state
__device__ int g_bar_cnt = 0;
__device__ volatile int g_bar_gen = 0;

// ======================= helpers =================
__device__ __forceinline__ uint32_t smem_u32(const void* p) {
    return (uint32_t)__cvta_generic_to_shared(p);
}
__device__ __forceinline__ void cp_async16(uint32_t dst, const void* src, int src_bytes) {
    asm volatile("cp.async.cg.shared.global [%0], [%1], 16, %2;"
                 :: "r"(dst), "l"(src), "r"(src_bytes));
}
#define CP_COMMIT() asm volatile("cp.async.commit_group;" ::: "memory")
#define CP_WAIT1()  asm volatile("cp.async.wait_group 1;" ::: "memory")
#define CP_WAIT2()  asm volatile("cp.async.wait_group 2;" ::: "memory")

__device__ __forceinline__ void ldsm_x4(uint32_t* r, uint32_t addr) {
    asm volatile("ldmatrix.sync.aligned.m8n8.x4.shared.b16 {%0,%1,%2,%3}, [%4];"
                 : "=r"(r[0]), "=r"(r[1]), "=r"(r[2]), "=r"(r[3]) : "r"(addr));
}
__device__ __forceinline__ void mma16816(float* d, const uint32_t* a, const uint32_t* b) {
    asm volatile(
        "mma.sync.aligned.m16n8k16.row.col.f32.f16.f16.f32 "
        "{%0,%1,%2,%3}, {%4,%5,%6,%7}, {%8,%9}, {%0,%1,%2,%3};"
        : "+f"(d[0]), "+f"(d[1]), "+f"(d[2]), "+f"(d[3])
        : "r"(a[0]), "r"(a[1]), "r"(a[2]), "r"(a[3]), "r"(b[0]), "r"(b[1]));
}

__device__ __forceinline__ void grid_bar() {
    __syncthreads();
    if (threadIdx.x == 0) {
        __threadfence();
        int gen = g_bar_gen;
        if (atomicAdd(&g_bar_cnt, 1) == GRID_SCAN - 1) {
            g_bar_cnt = 0;
            __threadfence();
            g_bar_gen = gen + 1;
        } else {
            while (g_bar_gen == gen) {}
        }
        __threadfence();
    }
    __syncthreads();
}

// ===== in-scan GEMM phase: C[128, 32@n0] = A[128,K]h @ W[.,K]h^T (+bias) ====
// 8 warps: wm = wid&3 (4 m-tiles of 32), wn = wid>>2 (2 n-tiles of 16).
__device__ void phase_gemm(const __half* __restrict__ A, int lda, int K,
                           const __half* __restrict__ W, int ldw,
                           const float* __restrict__ bias,
                           float* __restrict__ C, int ldc, int n0,
                           __half* sA, __half* sB)   // sA: 2*128*72, sB: 2*32*72
{
    const int tid = threadIdx.x;
    const int wid = tid >> 5, lane = tid & 31;
    const int wm = wid & 3, wn = wid >> 2;

    float acc[2][2][4];
#pragma unroll
    for (int i = 0; i < 2; i++)
#pragma unroll
        for (int j = 0; j < 2; j++)
#pragma unroll
            for (int q = 0; q < 4; q++) acc[i][j][q] = 0.f;

    const int NIT = K >> 6;  // BK = 64

#define PH_ISSUE(kt, st) do {                                                  \
        int k0 = (kt) << 6;                                                    \
        __half* pa = sA + (st) * (128 * 72);                                   \
        __half* pb = sB + (st) * (32 * 72);                                    \
        _Pragma("unroll")                                                      \
        for (int c = 0; c < 4; c++) {                                          \
            int idx = tid + 256 * c;                                           \
            int row = idx >> 3, q = (idx & 7) * 8;                             \
            cp_async16(smem_u32(pa + row * 72 + q),                            \
                       A + (size_t)row * lda + k0 + q, 16);                    \
        }                                                                      \
        { int row = tid >> 3, q = (tid & 7) * 8;                               \
          cp_async16(smem_u32(pb + row * 72 + q),                              \
                     W + (size_t)(n0 + row) * ldw + k0 + q, 16); }             \
        CP_COMMIT();                                                           \
    } while (0)

    PH_ISSUE(0, 0);
    for (int kt = 0; kt < NIT; kt++) {
        if (kt + 1 < NIT) { PH_ISSUE(kt + 1, (kt + 1) & 1); }
        else { CP_COMMIT(); }
        CP_WAIT1();
        __syncthreads();
        const __half* pa = sA + (kt & 1) * (128 * 72);
        const __half* pb = sB + (kt & 1) * (32 * 72);
#pragma unroll
        for (int ks = 0; ks < 4; ks++) {
            uint32_t a[2][4], b[4];
#pragma unroll
            for (int i = 0; i < 2; i++)
                ldsm_x4(a[i], smem_u32(pa + (wm * 32 + i * 16 + (lane & 15)) * 72
                                          + ks * 16 + (lane >> 4) * 8));
            ldsm_x4(b, smem_u32(pb + (wn * 16 + (lane & 7) + ((lane >> 4) << 3)) * 72
                                   + ks * 16 + ((lane >> 3) & 1) * 8));
#pragma unroll
            for (int i = 0; i < 2; i++)
#pragma unroll
                for (int j = 0; j < 2; j++)
                    mma16816(acc[i][j], a[i], &b[j * 2]);
        }
        __syncthreads();
    }
#undef PH_ISSUE

#pragma unroll
    for (int i = 0; i < 2; i++) {
        int m = wm * 32 + i * 16 + (lane >> 2);
#pragma unroll
        for (int j = 0; j < 2; j++) {
            int n = n0 + wn * 16 + j * 8 + (lane & 3) * 2;
            float b0 = bias ? bias[n] : 0.f;
            float b1 = bias ? bias[n + 1] : 0.f;
            C[(size_t)m * ldc + n]           = acc[i][j][0] + b0;
            C[(size_t)m * ldc + n + 1]       = acc[i][j][1] + b1;
            C[(size_t)(m + 8) * ldc + n]     = acc[i][j][2] + b0;
            C[(size_t)(m + 8) * ldc + n + 1] = acc[i][j][3] + b1;
        }
    }
}

// =================== persistent fused scan kernel ===========================
// grid = 128 CTAs x 256 threads. CTA b owns batch row b for attention + LSTM.
// dynamic smem layout (bytes):
//  [0, 26624)        sHp   half[26*512]   Hproj[b] fp16 (resident all steps)
//  [26624, 79872)    sBH   float[26*512]  batch_H[b] fp32 (resident)
//  [79872, 81920)    sSC   float[512]     score_W
//  [81920, 83968)    sPh   float[512]     ph[b] staging
//  [83968, 120832)   sA    half 2*128*72  gemm stage
//  [120832, 130048)  sB    half 2*32*72
#define SMEM_SCAN 130048

__global__ __launch_bounds__(256)
void scan_kernel(const float* __restrict__ batch_H,
                 const float* __restrict__ score_W,
                 const float* __restrict__ h2h_b,
                 const int* __restrict__ text)
{
    extern __shared__ char dsm[];
    __half* sHp = (__half*)dsm;
    float*  sBH = (float*)(dsm + 26624);
    float*  sSC = (float*)(dsm + 79872);
    float*  sPh = (float*)(dsm + 81920);
    __half* sA  = (__half*)(dsm + 83968);
    __half* sB  = (__half*)(dsm + 120832);
    __shared__ float s_e[32];

    const int b   = blockIdx.x;
    const int tid = threadIdx.x;
    const int wid = tid >> 5, lane = tid & 31;

    // ---- load persistent per-b data ----
    for (int i = tid; i < T_ * 512; i += 256) {
        sHp[i] = __float2half(g_Hproj[(size_t)b * T_ * 512 + i]);
        sBH[i] = batch_H[(size_t)b * T_ * 512 + i];
    }
#pragma unroll
    for (int i = 0; i < 2; i++) sSC[tid + 256 * i] = score_W[tid + 256 * i];
    __syncthreads();

    // LSTM cell state in registers (CTA b, elements tid and tid+256)
    float c0 = 0.f, c1 = 0.f;

    for (int s = 0; s < STEPS_; s++) {
        // ---- P1: ph = h @ h2h^T + b  (CTAs 0..15, 32 cols each) ----
        if (b < 16)
            phase_gemm(g_xh + 512, 1024, 512, g_h2h_h, 512,
                       h2h_b, g_ph, 512, b * 32, sA, sB);
        grid_bar();

        // ---- P2: attention for batch b (smem-resident Hproj/batch_H) ----
#pragma unroll
        for (int i = 0; i < 2; i++)
            sPh[tid + 256 * i] = g_ph[b * 512 + tid + 256 * i];
        __syncthreads();
        for (int t = wid; t < T_; t += 8) {
            const __half* hp = sHp + t * 512;
            float sum = 0.f;
            for (int j = lane; j < 512; j += 32)
                sum += sSC[j] * tanhf(__half2float(hp[j]) + sPh[j]);
#pragma unroll
            for (int o = 16; o > 0; o >>= 1)
                sum += __shfl_xor_sync(0xffffffffu, sum, o);
            if (lane == 0) s_e[t] = sum;
        }
        __syncthreads();
        if (tid < 32) {
            float v = (tid < T_) ? s_e[tid] : -1e30f;
            float m = v;
#pragma unroll
            for (int o = 16; o > 0; o >>= 1)
                m = fmaxf(m, __shfl_xor_sync(0xffffffffu, m, o));
            float e = (tid < T_) ? expf(v - m) : 0.f;
            float ssum = e;
#pragma unroll
            for (int o = 16; o > 0; o >>= 1)
                ssum += __shfl_xor_sync(0xffffffffu, ssum, o);
            if (tid < T_) s_e[tid] = e / ssum;
        }
        __syncthreads();
#pragma unroll
        for (int i = 0; i < 2; i++) {
            int j = tid + 256 * i;
            float acc = 0.f;
#pragma unroll
            for (int t = 0; t < T_; t++)
                acc += s_e[t] * sBH[t * 512 + j];
            g_xh[b * 1024 + j] = __float2half(acc);
        }
        grid_bar();

        // ---- P3: gates = [ctx|h] @ Wg^T  (CTAs 0..63, 32 cols each) ----
        if (b < 64)
            phase_gemm(g_xh, 1024, 1024, g_Wg, 1024,
                       nullptr, g_gates, 2048, b * 32, sA, sB);
        grid_bar();

        // ---- P4: LSTM pointwise for batch b ----
        {
            const int cls = text[b * STEPS_ + s];
            const float* wt = g_Wt + cls * 2048;
#pragma unroll
            for (int i = 0; i < 2; i++) {
                int j = tid + 256 * i;
                float gi = g_gates[b * 2048 + j]        + wt[j];
                float gf = g_gates[b * 2048 + 512 + j]  + wt[512 + j];
                float gg = g_gates[b * 2048 + 1024 + j] + wt[1024 + j];
                float go = g_gates[b * 2048 + 1536 + j] + wt[1536 + j];
                float si = 1.f / (1.f + expf(-gi));
                float sf = 1.f / (1.f + expf(-gf));
                float so = 1.f / (1.f + expf(-go));
                float tg = tanhf(gg);
                float cc = i == 0 ? c0 : c1;
                float cn = sf * cc + si * tg;
                float hn = so * tanhf(cn);
                if (i == 0) c0 = cn; else c1 = cn;
                __half hh = __float2half(hn);
                g_xh[b * 1024 + 512 + j] = hh;
                g_Hs_h[((size_t)b * STEPS_ + s) * 512 + j] = hh;
            }
        }
        grid_bar();
    }
}

// ============ head GEMM: out[3328,N] = A_h @ W_h^T + bias ==================
// BM=128 BN=128 BK=64, 3-stage cp.async, 8 warps (2x4), warp tile 64x32.
#define HD_SMEM (6 * 128 * 72 * 2)   // 110592 bytes

__global__ __launch_bounds__(256, 2)
void head_gemm_mma(const __half* __restrict__ A,   // [3328, 512]
                   const __half* __restrict__ W,   // [Ntot, 512]
                   const float* __restrict__ bias,
                   float* __restrict__ out,
                   int Ntot)
{
    extern __shared__ __half hsm[];
    __half* sA = hsm;                  // 3 stages of 128x72
    __half* sB = hsm + 3 * 128 * 72;

    const int tid = threadIdx.x;
    const int wid = tid >> 5, lane = tid & 31;
    const int wm = wid >> 2, wn = wid & 3;     // 2 x 4 warp grid
    const int m0 = blockIdx.x * 128;
    const int n0 = blockIdx.y * 128;

    float acc[4][4][4];
#pragma unroll
    for (int i = 0; i < 4; i++)
#pragma unroll
        for (int j = 0; j < 4; j++)
#pragma unroll
            for (int q = 0; q < 4; q++) acc[i][j][q] = 0.f;

#define HD_ISSUE(kt) do {                                                      \
        int st = (kt) % 3;                                                     \
        int k0 = (kt) << 6;                                                    \
        __half* pa = sA + st * (128 * 72);                                     \
        __half* pb = sB + st * (128 * 72);                                     \
        _Pragma("unroll")                                                      \
        for (int c = 0; c < 4; c++) {                                          \
            int idx = tid + 256 * c;                                           \
            int row = idx >> 3, q = (idx & 7) * 8;                             \
            cp_async16(smem_u32(pa + row * 72 + q),                            \
                       A + (size_t)(m0 + row) * 512 + k0 + q, 16);             \
            cp_async16(smem_u32(pb + row * 72 + q),                            \
                       W + (size_t)(n0 + row) * 512 + k0 + q,                  \
                       (n0 + row < Ntot) ? 16 : 0);                            \
        }                                                                      \
        CP_COMMIT();                                                           \
    } while (0)

    HD_ISSUE(0);
    HD_ISSUE(1);
    for (int kt = 0; kt < 8; kt++) {
        if (kt + 2 < 8) { HD_ISSUE(kt + 2); } else { CP_COMMIT(); }
        CP_WAIT2();
        __syncthreads();
        const __half* pa = sA + (kt % 3) * (128 * 72);
        const __half* pb = sB + (kt % 3) * (128 * 72);
#pragma unroll
        for (int ks = 0; ks < 4; ks++) {
            uint32_t a[4][4], bfr[2][4];
#pragma unroll
            for (int i = 0; i < 4; i++)
                ldsm_x4(a[i], smem_u32(pa + (wm * 64 + i * 16 + (lane & 15)) * 72
                                          + ks * 16 + (lane >> 4) * 8));
#pragma unroll
            for (int j = 0; j < 2; j++)
                ldsm_x4(bfr[j], smem_u32(pb + (wn * 32 + j * 16 + (lane & 7)
                                              + ((lane >> 4) << 3)) * 72
                                            + ks * 16 + ((lane >> 3) & 1) * 8));
#pragma unroll
            for (int i = 0; i < 4; i++)
#pragma unroll
                for (int j = 0; j < 4; j++)
                    mma16816(acc[i][j], a[i], &bfr[j >> 1][(j & 1) * 2]);
        }
        __syncthreads();
    }
#undef HD_ISSUE

#pragma unroll
    for (int i = 0; i < 4; i++) {
        int mBase = m0 + wm * 64 + i * 16 + (lane >> 2);
#pragma unroll
        for (int j = 0; j < 4; j++) {
            int n = n0 + wn * 32 + j * 8 + (lane & 3) * 2;
            if (n < Ntot) {
                float b0 = bias[n];
                float b1 = (n + 1 < Ntot) ? bias[n + 1] : 0.f;
                float* p0 = out + (size_t)mBase * Ntot + n;
                float* p1 = out + (size_t)(mBase + 8) * Ntot + n;
                p0[0] = acc[i][j][0] + b0;
                p1[0] = acc[i][j][2] + b0;
                if (n + 1 < Ntot) {
                    p0[1] = acc[i][j][1] + b1;
                    p1[1] = acc[i][j][3] + b1;
                }
            }
        }
    }
}

// ---------------- prep kernels ----------------
__global__ void cvt_half(const float* __restrict__ src, __half* __restrict__ dst, int n4) {
    int i = blockIdx.x * blockDim.x + threadIdx.x;
    if (i < n4) {
        float4 v = ((const float4*)src)[i];
        ((__half2*)dst)[2 * i]     = __floats2half2_rn(v.x, v.y);
        ((__half2*)dst)[2 * i + 1] = __floats2half2_rn(v.z, v.w);
    }
}

__global__ void zero_xh_kernel() {
    int i = blockIdx.x * blockDim.x + threadIdx.x;
    if (i < B_ * 1024) g_xh[i] = __float2half(0.f);
}

// Wg[n][k] = k<512 ? Wih[n*550+k] : Whh[n*512+k-512]
__global__ void build_Wg(const float* __restrict__ Wih, const float* __restrict__ Whh) {
    int i = blockIdx.x * blockDim.x + threadIdx.x;   // over 2048*1024
    if (i < 2048 * 1024) {
        int n = i >> 10, k = i & 1023;
        float v = (k < 512) ? Wih[(size_t)n * 550 + k] : Whh[(size_t)n * 512 + k - 512];
        g_Wg[i] = __float2half(v);
    }
}

// Wt[c][n] = Wih[n*550 + 512 + c] + bih[n] + bhh[n]
__global__ void build_Wt(const float* __restrict__ Wih,
                         const float* __restrict__ bih,
                         const float* __restrict__ bhh) {
    int c = blockIdx.x;
    for (int n = threadIdx.x; n < 2048; n += blockDim.x)
        g_Wt[c * 2048 + n] = Wih[(size_t)n * 550 + 512 + c] + bih[n] + bhh[n];
}

// ---------------- fp32 GEMM (Hproj): C = A[M,K] @ W[N,K]^T ----------------
__global__ __launch_bounds__(256)
void gemm_nt(const float* __restrict__ A, int lda,
             const float* __restrict__ W, int ldw,
             const float* __restrict__ bias,
             float* __restrict__ C, long long ldc,
             int N, int K)
{
    __shared__ float As[16][132];
    __shared__ float Ws[16][132];
    const int tid = threadIdx.x;
    const int m0 = blockIdx.y * 128;
    const int n0 = blockIdx.x * 128;
    const int tx = tid & 15, ty = tid >> 4;
    float acc[8][8];
#pragma unroll
    for (int i = 0; i < 8; i++)
#pragma unroll
        for (int j = 0; j < 8; j++) acc[i][j] = 0.f;
    const int lr = tid >> 2, lk = (tid & 3) * 4;
    for (int k0 = 0; k0 < K; k0 += 16) {
#pragma unroll
        for (int i = 0; i < 2; i++) {
            int r = lr + 64 * i;
            float4 v = *(const float4*)&A[(long long)(m0 + r) * lda + k0 + lk];
            As[lk + 0][r] = v.x; As[lk + 1][r] = v.y;
            As[lk + 2][r] = v.z; As[lk + 3][r] = v.w;
            float4 w = make_float4(0.f, 0.f, 0.f, 0.f);
            if (n0 + r < N)
                w = *(const float4*)&W[(long long)(n0 + r) * ldw + k0 + lk];
            Ws[lk + 0][r] = w.x; Ws[lk + 1][r] = w.y;
            Ws[lk + 2][r] = w.z; Ws[lk + 3][r] = w.w;
        }
        __syncthreads();
#pragma unroll
        for (int k = 0; k < 16; k++) {
            float a[8], bb[8];
            *(float4*)&a[0] = *(const float4*)&As[k][ty * 8];
            *(float4*)&a[4] = *(const float4*)&As[k][ty * 8 + 4];
            *(float4*)&bb[0] = *(const float4*)&Ws[k][tx * 8];
            *(float4*)&bb[4] = *(const float4*)&Ws[k][tx * 8 + 4];
#pragma unroll
            for (int i = 0; i < 8; i++)
#pragma unroll
                for (int j = 0; j < 8; j++)
                    acc[i][j] += a[i] * bb[j];
        }
        __syncthreads();
    }
#pragma unroll
    for (int i = 0; i < 8; i++) {
        int m = m0 + ty * 8 + i;
#pragma unroll
        for (int j = 0; j < 8; j++) {
            int n = n0 + tx * 8 + j;
            if (n < N) {
                float v = acc[i][j];
                if (bias) v += bias[n];
                C[(long long)m * ldc + n] = v;
            }
        }
    }
}

// ---------------- launcher ----------------
extern "C" void kernel_launch(void* const* d_in, const int* in_sizes, int n_in,
                              void* d_out, int out_size)
{
    const float* batch_H = (const float*)d_in[0];
    const int*   text    = (const int*)  d_in[1];
    const float* i2h_W   = (const float*)d_in[2];
    const float* h2h_W   = (const float*)d_in[3];
    const float* h2h_b   = (const float*)d_in[4];
    const float* score_W = (const float*)d_in[5];
    const float* rnn_Wih = (const float*)d_in[6];
    const float* rnn_bih = (const float*)d_in[7];
    const float* rnn_Whh = (const float*)d_in[8];
    const float* rnn_bhh = (const float*)d_in[9];
    const float* char_W  = (const float*)d_in[10];
    const float* char_b  = (const float*)d_in[11];
    const float* bpe_W   = (const float*)d_in[12];
    const float* bpe_b   = (const float*)d_in[13];
    const float* wp_W    = (const float*)d_in[14];
    const float* wp_b    = (const float*)d_in[15];
    float* out = (float*)d_out;

    float *d_Hproj;
    __half *d_Hs_h, *d_char_h, *d_bpe_h, *d_wp_h, *d_h2h_h;
    cudaGetSymbolAddress((void**)&d_Hproj,  g_Hproj);
    cudaGetSymbolAddress((void**)&d_Hs_h,   g_Hs_h);
    cudaGetSymbolAddress((void**)&d_char_h, g_char_h);
    cudaGetSymbolAddress((void**)&d_bpe_h,  g_bpe_h);
    cudaGetSymbolAddress((void**)&d_wp_h,   g_wp_h);
    cudaGetSymbolAddress((void**)&d_h2h_h,  g_h2h_h);

    cudaFuncSetAttribute(scan_kernel,
                         cudaFuncAttributeMaxDynamicSharedMemorySize, SMEM_SCAN);
    cudaFuncSetAttribute(head_gemm_mma,
                         cudaFuncAttributeMaxDynamicSharedMemorySize, HD_SMEM);

    // ---- prep (all independent) ----
    zero_xh_kernel<<<(B_ * 1024 + 255) / 256, 256>>>();
    cvt_half<<<(H_ * H_ / 4 + 255) / 256, 256>>>(h2h_W, d_h2h_h, H_ * H_ / 4);
    build_Wg<<<(2048 * 1024 + 255) / 256, 256>>>(rnn_Wih, rnn_Whh);
    build_Wt<<<NC_, 256>>>(rnn_Wih, rnn_bih, rnn_bhh);
    cvt_half<<<(NC_ * H_ / 4 + 255) / 256, 256>>>(char_W, d_char_h, NC_ * H_ / 4);
    cvt_half<<<(BPE_ * H_ / 4 + 255) / 256, 256>>>(bpe_W, d_bpe_h, BPE_ * H_ / 4);
    cvt_half<<<(WP_ * H_ / 4 + 255) / 256, 256>>>(wp_W, d_wp_h, WP_ * H_ / 4);

    // Hproj = batch_H @ i2h_W^T  (fp32)
    gemm_nt<<<dim3(4, 26), 256>>>(batch_H, 512, i2h_W, 512, nullptr,
                                  d_Hproj, 512, 512, 512);

    // ---- fused persistent scan ----
    scan_kernel<<<GRID_SCAN, 256, SMEM_SCAN>>>(batch_H, score_W, h2h_b, text);

    // ---- output heads ----
    const long long off_bpe = (long long)ROWS_ * NC_;
    const long long off_wp  = off_bpe + (long long)ROWS_ * BPE_;

    head_gemm_mma<<<dim3(26, 1), 256, HD_SMEM>>>(d_Hs_h, d_char_h, char_b, out, NC_);
    head_gemm_mma<<<dim3(26, (BPE_ + 127) / 128), 256, HD_SMEM>>>(
        d_Hs_h, d_bpe_h, bpe_b, out + off_bpe, BPE_);
    head_gemm_mma<<<dim3(26, (WP_ + 127) / 128), 256, HD_SMEM>>>(
        d_Hs_h, d_wp_h, wp_b, out + off_wp, WP_);
}